// round 11
// baseline (speedup 1.0000x reference)
#include <cuda_runtime.h>
#include <cuda_fp16.h>
#include <math.h>

#define NN 100000
#define EE 3200000
#define GG 64
#define LL 3

// ---- scratch (static device globals; no runtime allocation) ----
__device__ int   g_cnt[NN];
__device__ int   g_cur[NN];
__device__ int   g_off[NN + 1];
__device__ float g_dinv[NN];
__device__ unsigned long long g_edges[EE];   // low32: src idx, high32: norm bits
__device__ __half g_xwh[(size_t)NN * 128];   // per-layer linear output [N,128] fp16
__device__ float4 g_hjk4[(size_t)NN * 96];   // JK concat buffer [N,384] fp32
__device__ float g_gsum[GG * 384];
__device__ int   g_gcnt[GG];

// ---------------------------------------------------------------
__global__ void __launch_bounds__(256) k_zero_nodes() {
    int i = blockIdx.x * blockDim.x + threadIdx.x;
    if (i < NN) { g_cnt[i] = 0; g_cur[i] = 0; }
}

__global__ void __launch_bounds__(256) k_count(const int* __restrict__ ei) {
    int i = blockIdx.x * blockDim.x + threadIdx.x;
    if (i < EE) {
        int c = ei[EE + i];               // col (destination), int32
        atomicAdd(&g_cnt[c], 1);
    }
}

// single-block exclusive scan of g_cnt -> g_off  (+ fused dinv)
__global__ void __launch_bounds__(1024) k_scan() {
    __shared__ int s[1024];
    const int ITEMS = (NN + 1023) / 1024;   // 98
    int t = threadIdx.x;
    int base = t * ITEMS;
    int local = 0;
    for (int i = 0; i < ITEMS; i++) {
        int idx = base + i;
        if (idx < NN) local += g_cnt[idx];
    }
    s[t] = local;
    __syncthreads();
    for (int o = 1; o < 1024; o <<= 1) {
        int v = (t >= o) ? s[t - o] : 0;
        __syncthreads();
        s[t] += v;
        __syncthreads();
    }
    int run = s[t] - local;   // exclusive prefix
    for (int i = 0; i < ITEMS; i++) {
        int idx = base + i;
        if (idx < NN) {
            int c = g_cnt[idx];
            g_off[idx] = run; run += c;
            g_dinv[idx] = rsqrtf((float)(c + 1));   // deg includes self loop
        }
    }
    if (t == 0) g_off[NN] = EE;
}

__global__ void __launch_bounds__(256) k_scatter(const int* __restrict__ ei) {
    int i = blockIdx.x * blockDim.x + threadIdx.x;
    if (i < EE) {
        int r = ei[i];
        int c = ei[EE + i];
        int pos = g_off[c] + atomicAdd(&g_cur[c], 1);
        float nm = g_dinv[r] * g_dinv[c];
        g_edges[pos] = (unsigned long long)(unsigned)r |
                       ((unsigned long long)__float_as_uint(nm) << 32);
    }
}

// xw = h @ W_l : register-tiled. 256 threads, 64 rows x 128 cols per block,
// each thread computes a 4x8 tile. h tile fp16 in smem (16KB), W fp32 (32KB).
__global__ void __launch_bounds__(256) k_gemm(const float* __restrict__ x,
                                              const float* __restrict__ Wc, int l) {
    __shared__ float  sW[8192];        // [p][k][j]  (2 parts of 64x64)
    __shared__ __half sH[64 * 128];    // [row][c]
    int t = threadIdx.x;
    const float* W = Wc + l * 8192;
    const float* in = (l == 0) ? x : ((const float*)g_hjk4 + (size_t)(l - 1) * 128);
    int stride = (l == 0) ? 128 : 384;
    int rowBase = blockIdx.x * 64;

    for (int i = t; i < 8192; i += 256) sW[i] = W[i];
    for (int i = t; i < 2048; i += 256) {          // 64 rows x 32 float4
        int r = i >> 5, c4 = i & 31;
        int row = rowBase + r;
        float4 v = (row < NN) ? ((const float4*)(in + (size_t)row * stride))[c4]
                              : make_float4(0.f, 0.f, 0.f, 0.f);
        *(__half2*)&sH[r * 128 + c4 * 4]     = __floats2half2_rn(v.x, v.y);
        *(__half2*)&sH[r * 128 + c4 * 4 + 2] = __floats2half2_rn(v.z, v.w);
    }
    __syncthreads();

    int ct = t & 15, rt = t >> 4;          // 16 col-threads x 16 row-threads
    int col0 = ct * 8;
    int part = col0 >> 6, wcol = col0 & 63;
    int r0 = rt * 4;
    const float*  wp = sW + part * 4096 + wcol;
    const __half* hp = sH + r0 * 128 + part * 64;

    float acc[4][8];
#pragma unroll
    for (int i = 0; i < 4; i++)
#pragma unroll
        for (int j = 0; j < 8; j++) acc[i][j] = 0.f;

#pragma unroll 8
    for (int k = 0; k < 64; k++) {
        float h0 = __half2float(hp[k]);
        float h1 = __half2float(hp[128 + k]);
        float h2 = __half2float(hp[256 + k]);
        float h3 = __half2float(hp[384 + k]);
        float4 wa = *(const float4*)(wp + k * 64);
        float4 wb = *(const float4*)(wp + k * 64 + 4);
        acc[0][0] += h0 * wa.x; acc[0][1] += h0 * wa.y; acc[0][2] += h0 * wa.z; acc[0][3] += h0 * wa.w;
        acc[0][4] += h0 * wb.x; acc[0][5] += h0 * wb.y; acc[0][6] += h0 * wb.z; acc[0][7] += h0 * wb.w;
        acc[1][0] += h1 * wa.x; acc[1][1] += h1 * wa.y; acc[1][2] += h1 * wa.z; acc[1][3] += h1 * wa.w;
        acc[1][4] += h1 * wb.x; acc[1][5] += h1 * wb.y; acc[1][6] += h1 * wb.z; acc[1][7] += h1 * wb.w;
        acc[2][0] += h2 * wa.x; acc[2][1] += h2 * wa.y; acc[2][2] += h2 * wa.z; acc[2][3] += h2 * wa.w;
        acc[2][4] += h2 * wb.x; acc[2][5] += h2 * wb.y; acc[2][6] += h2 * wb.z; acc[2][7] += h2 * wb.w;
        acc[3][0] += h3 * wa.x; acc[3][1] += h3 * wa.y; acc[3][2] += h3 * wa.z; acc[3][3] += h3 * wa.w;
        acc[3][4] += h3 * wb.x; acc[3][5] += h3 * wb.y; acc[3][6] += h3 * wb.z; acc[3][7] += h3 * wb.w;
    }

#pragma unroll
    for (int i = 0; i < 4; i++) {
        int row = rowBase + r0 + i;
        if (row < NN) {
            __half hbuf[8];
#pragma unroll
            for (int j = 0; j < 8; j++) hbuf[j] = __float2half(acc[i][j]);
            *(uint4*)&g_xwh[(size_t)row * 128 + col0] = *(const uint4*)hbuf;
        }
    }
}

// aggregation + bias + BN + ReLU, fused. one warp per destination node.
// xw rows are fp16 (256B): lane owns 4 features via one uint2 (2x half2).
__global__ void __launch_bounds__(256) k_agg(const float* __restrict__ bc,
                                             const float* __restrict__ gam,
                                             const float* __restrict__ bet,
                                             const float* __restrict__ mea,
                                             const float* __restrict__ var, int l) {
    int warp = (blockIdx.x * blockDim.x + threadIdx.x) >> 5;
    int lane = threadIdx.x & 31;
    if (warp >= NN) return;
    int node = warp;

    const uint2* xw2 = (const uint2*)g_xwh;   // 32 uint2 per 128-half row

    float dn = g_dinv[node];
    float self = dn * dn;
    uint2 ra = xw2[(size_t)node * 32 + lane];
    float2 a0 = __half22float2(*(const half2*)&ra.x);
    float2 a1 = __half22float2(*(const half2*)&ra.y);
    float4 acc = make_float4(a0.x * self, a0.y * self, a1.x * self, a1.y * self);

    int beg = g_off[node], end = g_off[node + 1];
    for (int e = beg; e < end; e++) {
        unsigned long long pe = g_edges[e];
        int src = (int)(pe & 0xffffffffu);
        float nm = __uint_as_float((unsigned)(pe >> 32));
        uint2 rv = xw2[(size_t)src * 32 + lane];
        float2 v0 = __half22float2(*(const half2*)&rv.x);
        float2 v1 = __half22float2(*(const half2*)&rv.y);
        acc.x += v0.x * nm; acc.y += v0.y * nm; acc.z += v1.x * nm; acc.w += v1.y * nm;
    }

    const float4* b4v = (const float4*)(bc  + l * 128);
    const float4* g4v = (const float4*)(gam + l * 128);
    const float4* e4v = (const float4*)(bet + l * 128);
    const float4* m4v = (const float4*)(mea + l * 128);
    const float4* v4v = (const float4*)(var + l * 128);
    float4 b4 = b4v[lane], g4 = g4v[lane], e4 = e4v[lane], m4 = m4v[lane], vv4 = v4v[lane];

    float4 o;
    o.x = fmaxf(0.f, (acc.x + b4.x - m4.x) * rsqrtf(vv4.x + 1e-5f) * g4.x + e4.x);
    o.y = fmaxf(0.f, (acc.y + b4.y - m4.y) * rsqrtf(vv4.y + 1e-5f) * g4.y + e4.y);
    o.z = fmaxf(0.f, (acc.z + b4.z - m4.z) * rsqrtf(vv4.z + 1e-5f) * g4.z + e4.z);
    o.w = fmaxf(0.f, (acc.w + b4.w - m4.w) * rsqrtf(vv4.w + 1e-5f) * g4.w + e4.w);

    g_hjk4[(size_t)node * 96 + l * 32 + lane] = o;
}

__global__ void __launch_bounds__(256) k_zero_pool() {
    int i = blockIdx.x * blockDim.x + threadIdx.x;
    if (i < GG * 384) g_gsum[i] = 0.f;
    if (i < GG)       g_gcnt[i] = 0;
}

// batch is sorted (int32): per-slab register accumulation, flush on graph change.
__global__ void __launch_bounds__(384) k_pool(const int* __restrict__ batch) {
    int f = threadIdx.x;               // 384 threads, one per feature
    const float* hjk = (const float*)g_hjk4;
    int n0 = blockIdx.x * 128;
    int n1 = n0 + 128; if (n1 > NN) n1 = NN;
    int prev = -1; float acc = 0.f; int cl = 0;
    for (int n = n0; n < n1; n++) {
        int g = batch[n];
        if (g != prev) {
            if (prev >= 0) {
                atomicAdd(&g_gsum[prev * 384 + f], acc);
                if (f == 0) atomicAdd(&g_gcnt[prev], cl);
            }
            prev = g; acc = 0.f; cl = 0;
        }
        acc += hjk[(size_t)n * 384 + f];
        cl++;
    }
    if (prev >= 0) {
        atomicAdd(&g_gsum[prev * 384 + f], acc);
        if (f == 0) atomicAdd(&g_gcnt[prev], cl);
    }
}

// mean -> FC1 + ReLU -> FC2 -> log_softmax. one block per graph.
__global__ void __launch_bounds__(128) k_head(const float* __restrict__ W1,
                                              const float* __restrict__ b1,
                                              const float* __restrict__ W2,
                                              const float* __restrict__ b2,
                                              float* __restrict__ out) {
    __shared__ float sp[384];
    __shared__ float r0s[128], r1s[128];
    int g = blockIdx.x, j = threadIdx.x;   // 128 threads
    float c = (float)g_gcnt[g]; if (c < 1.f) c = 1.f;
    float inv = 1.f / c;
    for (int idx = j; idx < 384; idx += 128) sp[idx] = g_gsum[g * 384 + idx] * inv;
    __syncthreads();
    float acc = b1[j];
    for (int k = 0; k < 384; k++) acc += sp[k] * W1[k * 128 + j];
    float z = fmaxf(acc, 0.f);
    r0s[j] = z * W2[j * 2 + 0];
    r1s[j] = z * W2[j * 2 + 1];
    __syncthreads();
    for (int s = 64; s > 0; s >>= 1) {
        if (j < s) { r0s[j] += r0s[j + s]; r1s[j] += r1s[j + s]; }
        __syncthreads();
    }
    if (j == 0) {
        float z0 = r0s[0] + b2[0], z1 = r1s[0] + b2[1];
        float m = fmaxf(z0, z1);
        float lse = m + logf(expf(z0 - m) + expf(z1 - m));
        out[g * 2 + 0] = z0 - lse;
        out[g * 2 + 1] = z1 - lse;
    }
}

// ---------------------------------------------------------------
extern "C" void kernel_launch(void* const* d_in, const int* in_sizes, int n_in,
                              void* d_out, int out_size) {
    const float* x     = (const float*)d_in[0];
    const int*   ei    = (const int*)d_in[1];      // int32 (JAX x64 disabled)
    const int*   batch = (const int*)d_in[2];      // int32
    const float* Wc    = (const float*)d_in[3];
    const float* bc    = (const float*)d_in[4];
    const float* gam   = (const float*)d_in[5];
    const float* bet   = (const float*)d_in[6];
    const float* mea   = (const float*)d_in[7];
    const float* var   = (const float*)d_in[8];
    const float* W1    = (const float*)d_in[9];
    const float* b1    = (const float*)d_in[10];
    const float* W2    = (const float*)d_in[11];
    const float* b2    = (const float*)d_in[12];
    float* out = (float*)d_out;

    k_zero_nodes<<<(NN + 255) / 256, 256>>>();
    k_count<<<(EE + 255) / 256, 256>>>(ei);
    k_scan<<<1, 1024>>>();
    k_scatter<<<(EE + 255) / 256, 256>>>(ei);

    for (int l = 0; l < LL; l++) {
        k_gemm<<<(NN + 63) / 64, 256>>>(x, Wc, l);
        k_agg<<<(NN * 32 + 255) / 256, 256>>>(bc, gam, bet, mea, var, l);
    }

    k_zero_pool<<<(GG * 384 + 255) / 256, 256>>>();
    k_pool<<<(NN + 127) / 128, 384>>>(batch);
    k_head<<<GG, 128>>>(W1, b1, W2, b2, out);
}

// round 13
// speedup vs baseline: 1.2308x; 1.2308x over previous
#include <cuda_runtime.h>
#include <cuda_fp16.h>
#include <math.h>

#define NN 100000
#define EE 3200000
#define GG 64
#define LL 3

// ---- scratch (static device globals; no runtime allocation) ----
__device__ int   g_cnt[NN];
__device__ int   g_cur[NN];
__device__ int   g_off[NN + 1];
__device__ float g_dinv[NN];
__device__ unsigned long long g_edges[EE];   // low32: src idx, high32: norm bits
__device__ __half g_xwh[(size_t)NN * 128];   // per-layer linear output [N,128] fp16
__device__ float4 g_hjk4[(size_t)NN * 96];   // JK concat buffer [N,384] fp32
__device__ float g_gsum[GG * 384];
__device__ int   g_gcnt[GG];
// W fragments: [l][p][k16][j8][lane] -> uint2 (b0,b1), fp16x2 each
__device__ uint2 g_wfrag[LL * 2 * 4 * 8 * 32];

// ---------------------------------------------------------------
__global__ void __launch_bounds__(256) k_zero_nodes() {
    int i = blockIdx.x * blockDim.x + threadIdx.x;
    if (i < NN) { g_cnt[i] = 0; g_cur[i] = 0; }
}

__global__ void __launch_bounds__(256) k_count(const int* __restrict__ ei) {
    int i = blockIdx.x * blockDim.x + threadIdx.x;
    if (i < EE) {
        int c = ei[EE + i];               // col (destination), int32
        atomicAdd(&g_cnt[c], 1);
    }
}

// single-block exclusive scan of g_cnt -> g_off  (+ fused dinv)
__global__ void __launch_bounds__(1024) k_scan() {
    __shared__ int s[1024];
    const int ITEMS = (NN + 1023) / 1024;   // 98
    int t = threadIdx.x;
    int base = t * ITEMS;
    int local = 0;
    for (int i = 0; i < ITEMS; i++) {
        int idx = base + i;
        if (idx < NN) local += g_cnt[idx];
    }
    s[t] = local;
    __syncthreads();
    for (int o = 1; o < 1024; o <<= 1) {
        int v = (t >= o) ? s[t - o] : 0;
        __syncthreads();
        s[t] += v;
        __syncthreads();
    }
    int run = s[t] - local;   // exclusive prefix
    for (int i = 0; i < ITEMS; i++) {
        int idx = base + i;
        if (idx < NN) {
            int c = g_cnt[idx];
            g_off[idx] = run; run += c;
            g_dinv[idx] = rsqrtf((float)(c + 1));   // deg includes self loop
        }
    }
    if (t == 0) g_off[NN] = EE;
}

__global__ void __launch_bounds__(256) k_scatter(const int* __restrict__ ei) {
    int i = blockIdx.x * blockDim.x + threadIdx.x;
    if (i < EE) {
        int r = ei[i];
        int c = ei[EE + i];
        int pos = g_off[c] + atomicAdd(&g_cur[c], 1);
        float nm = g_dinv[r] * g_dinv[c];
        g_edges[pos] = (unsigned long long)(unsigned)r |
                       ((unsigned long long)__float_as_uint(nm) << 32);
    }
}

// Pre-swizzle W into mma.m16n8k16 B-fragment order (fp16), once per launch.
// i -> [l][p][k16][j8][lane];  b0: k={tig*2,tig*2+1}, n=gid;  b1: k += 8.
__global__ void __launch_bounds__(256) k_wprep(const float* __restrict__ Wc) {
    int i = blockIdx.x * blockDim.x + threadIdx.x;
    if (i >= LL * 2 * 4 * 8 * 32) return;
    int lane = i & 31; int rest = i >> 5;
    int j8 = rest & 7; rest >>= 3;
    int k16 = rest & 3; rest >>= 2;
    int p = rest & 1; int l = rest >> 1;
    int gid = lane >> 2, tig = lane & 3;
    const float* W = Wc + ((l * 2 + p) * 4096);   // [64 k][64 j]
    int n = j8 * 8 + gid;
    int k0 = k16 * 16 + tig * 2;
    __half2 b0 = __floats2half2_rn(W[k0 * 64 + n],       W[(k0 + 1) * 64 + n]);
    __half2 b1 = __floats2half2_rn(W[(k0 + 8) * 64 + n], W[(k0 + 9) * 64 + n]);
    g_wfrag[i] = make_uint2(*(unsigned*)&b0, *(unsigned*)&b1);
}

// xw = h @ W_l via HMMA. 256 threads = 8 warps; block = 64 rows x 128 cols.
// Warp w: rows (w>>1)*16..+15, part p = w&1 (64 cols). 32 mma per warp.
#define SH_STRIDE 136   // conflict-free half2 A-frag loads
__global__ void __launch_bounds__(256) k_gemm(const float* __restrict__ x, int l) {
    __shared__ __half sH[64 * SH_STRIDE];
    int t = threadIdx.x;
    const float* in = (l == 0) ? x : ((const float*)g_hjk4 + (size_t)(l - 1) * 128);
    int stride = (l == 0) ? 128 : 384;
    int rowBase = blockIdx.x * 64;

    for (int i = t; i < 2048; i += 256) {          // 64 rows x 32 float4
        int r = i >> 5, c4 = i & 31;
        int row = rowBase + r;
        float4 v = (row < NN) ? ((const float4*)(in + (size_t)row * stride))[c4]
                              : make_float4(0.f, 0.f, 0.f, 0.f);
        __half* dst = &sH[r * SH_STRIDE + c4 * 4];
        *(__half2*)dst       = __floats2half2_rn(v.x, v.y);
        *(__half2*)(dst + 2) = __floats2half2_rn(v.z, v.w);
    }
    __syncthreads();

    int w = t >> 5, lane = t & 31;
    int r0 = (w >> 1) * 16, p = w & 1;
    int gid = lane >> 2, tig = lane & 3;

    // A fragments: 4 k16-tiles x 4 regs
    unsigned a[4][4];
    const __half* baseA = sH + p * 64;
#pragma unroll
    for (int k16 = 0; k16 < 4; k16++) {
        int k0 = k16 * 16 + tig * 2;
        a[k16][0] = *(const unsigned*)&baseA[(r0 + gid)     * SH_STRIDE + k0];
        a[k16][1] = *(const unsigned*)&baseA[(r0 + gid + 8) * SH_STRIDE + k0];
        a[k16][2] = *(const unsigned*)&baseA[(r0 + gid)     * SH_STRIDE + k0 + 8];
        a[k16][3] = *(const unsigned*)&baseA[(r0 + gid + 8) * SH_STRIDE + k0 + 8];
    }

    const uint2* wf = g_wfrag + ((l * 2 + p) * 4) * 8 * 32;
    int row1 = rowBase + r0 + gid;
    int row2 = row1 + 8;

#pragma unroll
    for (int j8 = 0; j8 < 8; j8++) {
        float c0 = 0.f, c1 = 0.f, c2 = 0.f, c3 = 0.f;
#pragma unroll
        for (int k16 = 0; k16 < 4; k16++) {
            uint2 b = wf[(k16 * 8 + j8) * 32 + lane];
            asm volatile(
                "mma.sync.aligned.m16n8k16.row.col.f32.f16.f16.f32 "
                "{%0,%1,%2,%3}, {%4,%5,%6,%7}, {%8,%9}, {%0,%1,%2,%3};"
                : "+f"(c0), "+f"(c1), "+f"(c2), "+f"(c3)
                : "r"(a[k16][0]), "r"(a[k16][1]), "r"(a[k16][2]), "r"(a[k16][3]),
                  "r"(b.x), "r"(b.y));
        }
        int col = p * 64 + j8 * 8 + tig * 2;
        if (row1 < NN) {
            __half2 h01 = __floats2half2_rn(c0, c1);
            *(__half2*)&g_xwh[(size_t)row1 * 128 + col] = h01;
        }
        if (row2 < NN) {
            __half2 h23 = __floats2half2_rn(c2, c3);
            *(__half2*)&g_xwh[(size_t)row2 * 128 + col] = h23;
        }
    }
}

// aggregation + bias + BN + ReLU, fused. one warp per destination node.
// xw rows are fp16 (256B): lane owns 4 features via one uint2 (2x half2).
__global__ void __launch_bounds__(256) k_agg(const float* __restrict__ bc,
                                             const float* __restrict__ gam,
                                             const float* __restrict__ bet,
                                             const float* __restrict__ mea,
                                             const float* __restrict__ var, int l) {
    int warp = (blockIdx.x * blockDim.x + threadIdx.x) >> 5;
    int lane = threadIdx.x & 31;
    if (warp >= NN) return;
    int node = warp;

    const uint2* xw2 = (const uint2*)g_xwh;   // 32 uint2 per 128-half row

    float dn = g_dinv[node];
    float self = dn * dn;
    uint2 ra = xw2[(size_t)node * 32 + lane];
    float2 a0 = __half22float2(*(const half2*)&ra.x);
    float2 a1 = __half22float2(*(const half2*)&ra.y);
    float4 acc = make_float4(a0.x * self, a0.y * self, a1.x * self, a1.y * self);

    int beg = g_off[node], end = g_off[node + 1];
    for (int e = beg; e < end; e++) {
        unsigned long long pe = g_edges[e];
        int src = (int)(pe & 0xffffffffu);
        float nm = __uint_as_float((unsigned)(pe >> 32));
        uint2 rv = xw2[(size_t)src * 32 + lane];
        float2 v0 = __half22float2(*(const half2*)&rv.x);
        float2 v1 = __half22float2(*(const half2*)&rv.y);
        acc.x += v0.x * nm; acc.y += v0.y * nm; acc.z += v1.x * nm; acc.w += v1.y * nm;
    }

    const float4* b4v = (const float4*)(bc  + l * 128);
    const float4* g4v = (const float4*)(gam + l * 128);
    const float4* e4v = (const float4*)(bet + l * 128);
    const float4* m4v = (const float4*)(mea + l * 128);
    const float4* v4v = (const float4*)(var + l * 128);
    float4 b4 = b4v[lane], g4 = g4v[lane], e4 = e4v[lane], m4 = m4v[lane], vv4 = v4v[lane];

    float4 o;
    o.x = fmaxf(0.f, (acc.x + b4.x - m4.x) * rsqrtf(vv4.x + 1e-5f) * g4.x + e4.x);
    o.y = fmaxf(0.f, (acc.y + b4.y - m4.y) * rsqrtf(vv4.y + 1e-5f) * g4.y + e4.y);
    o.z = fmaxf(0.f, (acc.z + b4.z - m4.z) * rsqrtf(vv4.z + 1e-5f) * g4.z + e4.z);
    o.w = fmaxf(0.f, (acc.w + b4.w - m4.w) * rsqrtf(vv4.w + 1e-5f) * g4.w + e4.w);

    g_hjk4[(size_t)node * 96 + l * 32 + lane] = o;
}

__global__ void __launch_bounds__(256) k_zero_pool() {
    int i = blockIdx.x * blockDim.x + threadIdx.x;
    if (i < GG * 384) g_gsum[i] = 0.f;
    if (i < GG)       g_gcnt[i] = 0;
}

// batch is sorted (int32): per-slab register accumulation, flush on graph change.
__global__ void __launch_bounds__(384) k_pool(const int* __restrict__ batch) {
    int f = threadIdx.x;               // 384 threads, one per feature
    const float* hjk = (const float*)g_hjk4;
    int n0 = blockIdx.x * 128;
    int n1 = n0 + 128; if (n1 > NN) n1 = NN;
    int prev = -1; float acc = 0.f; int cl = 0;
    for (int n = n0; n < n1; n++) {
        int g = batch[n];
        if (g != prev) {
            if (prev >= 0) {
                atomicAdd(&g_gsum[prev * 384 + f], acc);
                if (f == 0) atomicAdd(&g_gcnt[prev], cl);
            }
            prev = g; acc = 0.f; cl = 0;
        }
        acc += hjk[(size_t)n * 384 + f];
        cl++;
    }
    if (prev >= 0) {
        atomicAdd(&g_gsum[prev * 384 + f], acc);
        if (f == 0) atomicAdd(&g_gcnt[prev], cl);
    }
}

// mean -> FC1 + ReLU -> FC2 -> log_softmax. one block per graph.
__global__ void __launch_bounds__(128) k_head(const float* __restrict__ W1,
                                              const float* __restrict__ b1,
                                              const float* __restrict__ W2,
                                              const float* __restrict__ b2,
                                              float* __restrict__ out) {
    __shared__ float sp[384];
    __shared__ float r0s[128], r1s[128];
    int g = blockIdx.x, j = threadIdx.x;   // 128 threads
    float c = (float)g_gcnt[g]; if (c < 1.f) c = 1.f;
    float inv = 1.f / c;
    for (int idx = j; idx < 384; idx += 128) sp[idx] = g_gsum[g * 384 + idx] * inv;
    __syncthreads();
    float acc = b1[j];
    for (int k = 0; k < 384; k++) acc += sp[k] * W1[k * 128 + j];
    float z = fmaxf(acc, 0.f);
    r0s[j] = z * W2[j * 2 + 0];
    r1s[j] = z * W2[j * 2 + 1];
    __syncthreads();
    for (int s = 64; s > 0; s >>= 1) {
        if (j < s) { r0s[j] += r0s[j + s]; r1s[j] += r1s[j + s]; }
        __syncthreads();
    }
    if (j == 0) {
        float z0 = r0s[0] + b2[0], z1 = r1s[0] + b2[1];
        float m = fmaxf(z0, z1);
        float lse = m + logf(expf(z0 - m) + expf(z1 - m));
        out[g * 2 + 0] = z0 - lse;
        out[g * 2 + 1] = z1 - lse;
    }
}

// ---------------------------------------------------------------
extern "C" void kernel_launch(void* const* d_in, const int* in_sizes, int n_in,
                              void* d_out, int out_size) {
    const float* x     = (const float*)d_in[0];
    const int*   ei    = (const int*)d_in[1];      // int32 (JAX x64 disabled)
    const int*   batch = (const int*)d_in[2];      // int32
    const float* Wc    = (const float*)d_in[3];
    const float* bc    = (const float*)d_in[4];
    const float* gam   = (const float*)d_in[5];
    const float* bet   = (const float*)d_in[6];
    const float* mea   = (const float*)d_in[7];
    const float* var   = (const float*)d_in[8];
    const float* W1    = (const float*)d_in[9];
    const float* b1    = (const float*)d_in[10];
    const float* W2    = (const float*)d_in[11];
    const float* b2    = (const float*)d_in[12];
    float* out = (float*)d_out;

    k_zero_nodes<<<(NN + 255) / 256, 256>>>();
    k_count<<<(EE + 255) / 256, 256>>>(ei);
    k_scan<<<1, 1024>>>();
    k_scatter<<<(EE + 255) / 256, 256>>>(ei);
    k_wprep<<<(LL * 2 * 4 * 8 * 32 + 255) / 256, 256>>>(Wc);

    for (int l = 0; l < LL; l++) {
        k_gemm<<<(NN + 63) / 64, 256>>>(x, l);
        k_agg<<<(NN * 32 + 255) / 256, 256>>>(bc, gam, bet, mea, var, l);
    }

    k_zero_pool<<<(GG * 384 + 255) / 256, 256>>>();
    k_pool<<<(NN + 127) / 128, 384>>>(batch);
    k_head<<<GG, 128>>>(W1, b1, W2, b2, out);
}